// round 15
// baseline (speedup 1.0000x reference)
#include <cuda_runtime.h>
#include <cuda_fp16.h>
#include <cstdint>
#include <cstddef>

#define BN 1024
#define DD 768
#define TT 512
#define VV 49408

#define PROJ_Z 4

// ------------------------- static device workspace --------------------------
__device__ float g_rowsum[BN];             // softmax denominators (scaled)
__device__ float g_norm[VV];               // ||emb_v|| (fp32)
__device__ __half g_kwPartH[PROJ_Z][BN * TT];      // proj split-K partials (fp16)
__device__ __half g_kwH[BN * TT];                  // normalized kw, fp16
__device__ __half g_embH[(size_t)VV * TT];         // NORMALIZED emb [v][t], fp16
__device__ __half g_probs[(size_t)BN * VV];        // scaled probs * ||emb_v||, fp16

// ------------------------------ helpers -------------------------------------
__device__ __forceinline__ uint32_t smem_u32(const void* p) {
    uint32_t a;
    asm("{ .reg .u64 t; cvta.to.shared.u64 t, %1; cvt.u32.u64 %0, t; }"
        : "=r"(a) : "l"(p));
    return a;
}
__device__ __forceinline__ void cp16(uint32_t s, const void* g) {
    asm volatile("cp.async.cg.shared.global [%0], [%1], 16;" :: "r"(s), "l"(g));
}
__device__ __forceinline__ void ldsm4(uint32_t* r, uint32_t addr) {
    asm volatile("ldmatrix.sync.aligned.m8n8.x4.shared.b16 {%0,%1,%2,%3}, [%4];"
        : "=r"(r[0]), "=r"(r[1]), "=r"(r[2]), "=r"(r[3]) : "r"(addr));
}
__device__ __forceinline__ void ldsm4t(uint32_t* r, uint32_t addr) {
    asm volatile("ldmatrix.sync.aligned.m8n8.x4.trans.shared.b16 {%0,%1,%2,%3}, [%4];"
        : "=r"(r[0]), "=r"(r[1]), "=r"(r[2]), "=r"(r[3]) : "r"(addr));
}
__device__ __forceinline__ void mma16816(float* c, const uint32_t* a, const uint32_t* b) {
    asm volatile("mma.sync.aligned.m16n8k16.row.col.f32.f16.f16.f32 "
        "{%0,%1,%2,%3}, {%4,%5,%6,%7}, {%8,%9}, {%0,%1,%2,%3};"
        : "+f"(c[0]), "+f"(c[1]), "+f"(c[2]), "+f"(c[3])
        : "r"(a[0]), "r"(a[1]), "r"(a[2]), "r"(a[3]), "r"(b[0]), "r"(b[1]));
}
__device__ __forceinline__ uint32_t pack2h(float a, float b) {
    const __half2 h = __floats2half2_rn(a, b);
    return *reinterpret_cast<const uint32_t*>(&h);
}
__device__ __forceinline__ uint4 cvt8(const float4 f0, const float4 f1) {
    return make_uint4(pack2h(f0.x, f0.y), pack2h(f0.z, f0.w),
                      pack2h(f1.x, f1.y), pack2h(f1.z, f1.w));
}

#define ROWA   144
#define ROWBT  272
#define PLANE  18432
#define STAGE  (2 * PLANE)            // 36864
#define NSTAGE 2
#define SMEMSZ (NSTAGE * STAGE + 512) // 74240 -> 2 CTAs/SM

#define PSCALE 16384.f

// =============================================================================
// GEMM1 (non-persistent, the measured-fastest variant): logits + exp epilogue.
// Grid (BN/128, VV/128), 512 thr, warp 32x32, static 8-chunk K loop.
// =============================================================================
__global__ __launch_bounds__(512, 2) void gemm1(int dummy)
{
    extern __shared__ char smem[];
    const uint32_t sbase = smem_u32(smem);
    const int tid = threadIdx.x;
    const int lane = tid & 31, wid = tid >> 5;
    const int warpM = wid & 3, warpN = wid >> 2;
    const int m0 = blockIdx.x * 128, n0 = blockIdx.y * 128;

    float* sNorm = (float*)(smem + NSTAGE * STAGE);
    if (tid < 128) sNorm[tid] = g_norm[n0 + tid];

    const uint32_t ch   = tid & 7;
    const uint32_t rowA = tid >> 3;
    uint32_t aOff = (uint32_t)(m0 + rowA) * TT + ch * 8;
    uint32_t bOff = (uint32_t)(n0 + rowA) * TT + ch * 8;
    const uint32_t aSo = rowA * ROWA + ch * 16;

    auto issue = [&](uint32_t st) {
        #pragma unroll
        for (int p = 0; p < 2; p++) {
            cp16(st + aSo + p * (64 * ROWA), g_kwH  + aOff + p * (64 * TT));
            cp16(st + PLANE + aSo + p * (64 * ROWA), g_embH + bOff + p * (64 * TT));
        }
        aOff += 64;
        bOff += 64;
    };

    const uint32_t saOff = (uint32_t)(warpM * 32 + (lane & 15)) * ROWA + ((lane >> 4) << 4);
    const uint32_t sbOff = PLANE + (uint32_t)(warpN * 32 + (lane & 15)) * ROWA
                         + ((lane >> 4) << 4);

    float acc[2][4][4];
    #pragma unroll
    for (int i = 0; i < 2; i++)
        #pragma unroll
        for (int j = 0; j < 4; j++)
            #pragma unroll
            for (int k = 0; k < 4; k++) acc[i][j][k] = 0.f;

    issue(sbase);
    asm volatile("cp.async.commit_group;" ::: "memory");
    issue(sbase + STAGE);
    asm volatile("cp.async.commit_group;" ::: "memory");

    #pragma unroll 1
    for (int c = 0; c < TT / 64; c++) {
        asm volatile("cp.async.wait_group 1;" ::: "memory");
        __syncthreads();
        const uint32_t st = sbase + (uint32_t)(c & 1) * STAGE;

        #pragma unroll
        for (int ks = 0; ks < 4; ks++) {
            const uint32_t ko = ks * 32;
            uint32_t a[2][4], b[2][4];
            #pragma unroll
            for (int mf = 0; mf < 2; mf++)
                ldsm4(a[mf], st + saOff + mf * (16 * ROWA) + ko);
            #pragma unroll
            for (int g = 0; g < 2; g++)
                ldsm4(b[g], st + sbOff + g * (16 * ROWA) + ko);
            #pragma unroll
            for (int mf = 0; mf < 2; mf++)
                #pragma unroll
                for (int nf = 0; nf < 4; nf++) {
                    uint32_t bf[2] = { b[nf >> 1][nf & 1], b[nf >> 1][2 + (nf & 1)] };
                    mma16816(acc[mf][nf], a[mf], bf);
                }
        }
        __syncthreads();
        if (c + 2 < TT / 64) issue(st);
        asm volatile("cp.async.commit_group;" ::: "memory");
    }

    #pragma unroll
    for (int mf = 0; mf < 2; mf++) {
        const int r0 = m0 + warpM * 32 + mf * 16 + (lane >> 2);
        float rs0 = 0.f, rs1 = 0.f;
        #pragma unroll
        for (int nf = 0; nf < 4; nf++) {
            const int cl = warpN * 32 + nf * 8 + (lane & 3) * 2;
            const int cb = n0 + cl;
            const float e0 = __expf(acc[mf][nf][0] * 10.f - 10.f) * PSCALE;
            const float e1 = __expf(acc[mf][nf][1] * 10.f - 10.f) * PSCALE;
            const float e2 = __expf(acc[mf][nf][2] * 10.f - 10.f) * PSCALE;
            const float e3 = __expf(acc[mf][nf][3] * 10.f - 10.f) * PSCALE;
            rs0 += e0 + e1;  rs1 += e2 + e3;
            const float w0 = sNorm[cl], w1 = sNorm[cl + 1];
            *(uint32_t*)&g_probs[(size_t)r0 * VV + cb] = pack2h(e0 * w0, e1 * w1);
            *(uint32_t*)&g_probs[(size_t)(r0 + 8) * VV + cb] = pack2h(e2 * w0, e3 * w1);
        }
        rs0 += __shfl_xor_sync(0xffffffffu, rs0, 1);
        rs0 += __shfl_xor_sync(0xffffffffu, rs0, 2);
        rs1 += __shfl_xor_sync(0xffffffffu, rs1, 1);
        rs1 += __shfl_xor_sync(0xffffffffu, rs1, 2);
        if ((lane & 3) == 0) {
            atomicAdd(&g_rowsum[r0],     rs0);
            atomicAdd(&g_rowsum[r0 + 8], rs1);
        }
    }
}

// =============================================================================
// GEMM2: VQ split-K (A=probs, B=embH trans) -> (1/rowsum)*atomicAdd out
// =============================================================================
__global__ __launch_bounds__(512, 2) void gemm2(float* __restrict__ outf)
{
    constexpr int NCHT = VV / 64;
    extern __shared__ char smem[];
    const uint32_t sbase = smem_u32(smem);
    const int tid = threadIdx.x;
    const int lane = tid & 31, wid = tid >> 5;
    const int warpM = wid & 3, warpN = wid >> 2;

    const int n0 = blockIdx.x * 128, m0 = blockIdx.y * 128;
    const int c0 = (int)(((long)NCHT * blockIdx.z) / gridDim.z);
    const int c1 = (int)(((long)NCHT * (blockIdx.z + 1)) / gridDim.z);
    const int nch = c1 - c0;

    const uint32_t ch   = tid & 7;
    const uint32_t rowA = tid >> 3;
    uint32_t aOff = (uint32_t)(m0 + rowA) * VV + (uint32_t)c0 * 64 + ch * 8;
    const uint32_t aSo = rowA * ROWA + ch * 16;
    const uint32_t rb = tid >> 4, cb2 = tid & 15;
    uint32_t bOff = ((uint32_t)c0 * 64 + rb) * TT + (uint32_t)n0 + cb2 * 8;
    const uint32_t bSo = rb * ROWBT + cb2 * 16;

    auto issue = [&](uint32_t st) {
        #pragma unroll
        for (int p = 0; p < 2; p++) {
            cp16(st + aSo + p * (64 * ROWA), g_probs + aOff + p * (64 * VV));
            cp16(st + PLANE + bSo + p * (32 * ROWBT), g_embH + bOff + p * (32 * TT));
        }
        aOff += 64;
        bOff += 64 * TT;
    };

    const uint32_t saOff = (uint32_t)(warpM * 32 + (lane & 15)) * ROWA + ((lane >> 4) << 4);
    const uint32_t sbOff = PLANE + (uint32_t)((lane & 7) + ((lane >> 4) << 3)) * ROWBT
                         + (uint32_t)(warpN * 32 + ((lane >> 3) & 1) * 8) * 2;

    float acc[2][4][4];
    #pragma unroll
    for (int i = 0; i < 2; i++)
        #pragma unroll
        for (int j = 0; j < 4; j++)
            #pragma unroll
            for (int k = 0; k < 4; k++) acc[i][j][k] = 0.f;

    issue(sbase);
    asm volatile("cp.async.commit_group;" ::: "memory");
    issue(sbase + STAGE);
    asm volatile("cp.async.commit_group;" ::: "memory");

    for (int c = 0; c < nch; c++) {
        asm volatile("cp.async.wait_group 1;" ::: "memory");
        __syncthreads();
        const uint32_t st = sbase + (uint32_t)(c & 1) * STAGE;

        #pragma unroll
        for (int ks = 0; ks < 4; ks++) {
            const uint32_t ko = ks * 32;
            uint32_t a[2][4], b[2][4];
            #pragma unroll
            for (int mf = 0; mf < 2; mf++)
                ldsm4(a[mf], st + saOff + mf * (16 * ROWA) + ko);
            #pragma unroll
            for (int g = 0; g < 2; g++)
                ldsm4t(b[g], st + sbOff + ks * (16 * ROWBT) + g * 32);
            #pragma unroll
            for (int mf = 0; mf < 2; mf++)
                #pragma unroll
                for (int nf = 0; nf < 4; nf++) {
                    uint32_t bf[2] = { b[nf >> 1][nf & 1], b[nf >> 1][2 + (nf & 1)] };
                    mma16816(acc[mf][nf], a[mf], bf);
                }
        }
        __syncthreads();
        if (c + 2 < nch) issue(st);
        asm volatile("cp.async.commit_group;" ::: "memory");
    }

    #pragma unroll
    for (int mf = 0; mf < 2; mf++) {
        const int r0 = m0 + warpM * 32 + mf * 16 + (lane >> 2);
        const float s0 = 1.f / g_rowsum[r0];
        const float s1 = 1.f / g_rowsum[r0 + 8];
        #pragma unroll
        for (int nf = 0; nf < 4; nf++) {
            const int cb = n0 + warpN * 32 + nf * 8 + (lane & 3) * 2;
            atomicAdd(&outf[(size_t)r0 * TT + cb],           acc[mf][nf][0] * s0);
            atomicAdd(&outf[(size_t)r0 * TT + cb + 1],       acc[mf][nf][1] * s0);
            atomicAdd(&outf[(size_t)(r0 + 8) * TT + cb],     acc[mf][nf][2] * s1);
            atomicAdd(&outf[(size_t)(r0 + 8) * TT + cb + 1], acc[mf][nf][3] * s1);
        }
    }
}

// =============================================================================
// Projection on tensor path, on-the-fly fp32->fp16 conversion, fp16 partials.
// =============================================================================
__global__ __launch_bounds__(512, 1)
void proj_gemm(const float* __restrict__ audio, const float* __restrict__ W)
{
    constexpr int NCH = (DD / 64) / PROJ_Z;   // 3
    extern __shared__ char smem[];
    const uint32_t sbase = smem_u32(smem);
    const int tid = threadIdx.x;
    const int lane = tid & 31, wid = tid >> 5;
    const int warpM = wid & 3, warpN = wid >> 2;

    const int n0 = blockIdx.x * 128, m0 = blockIdx.y * 128;
    const int c0 = blockIdx.z * NCH;

    const uint32_t ch   = tid & 7;
    const uint32_t rowA = tid >> 3;
    const uint32_t aSo = rowA * ROWA + ch * 16;
    const uint32_t rb = tid >> 4, cb2 = tid & 15;
    const uint32_t bSo = rb * ROWBT + cb2 * 16;

    float4 ra[2][2], rbv[2][2];
    auto load_regs = [&](int c) {
        #pragma unroll
        for (int p = 0; p < 2; p++) {
            const float* pa = audio + (size_t)(m0 + rowA + p * 64) * DD
                            + (c0 + c) * 64 + ch * 8;
            ra[p][0] = ((const float4*)pa)[0];
            ra[p][1] = ((const float4*)pa)[1];
            const float* pb = W + (size_t)((c0 + c) * 64 + rb + p * 32) * TT
                            + n0 + cb2 * 8;
            rbv[p][0] = ((const float4*)pb)[0];
            rbv[p][1] = ((const float4*)pb)[1];
        }
    };
    auto store_smem = [&]() {
        #pragma unroll
        for (int p = 0; p < 2; p++) {
            *(uint4*)(smem + aSo + p * (64 * ROWA)) = cvt8(ra[p][0], ra[p][1]);
            *(uint4*)(smem + PLANE + bSo + p * (32 * ROWBT)) = cvt8(rbv[p][0], rbv[p][1]);
        }
    };

    const uint32_t saOff = (uint32_t)(warpM * 32 + (lane & 15)) * ROWA + ((lane >> 4) << 4);
    const uint32_t sbOff = PLANE + (uint32_t)((lane & 7) + ((lane >> 4) << 3)) * ROWBT
                         + (uint32_t)(warpN * 32 + ((lane >> 3) & 1) * 8) * 2;

    float acc[2][4][4];
    #pragma unroll
    for (int i = 0; i < 2; i++)
        #pragma unroll
        for (int j = 0; j < 4; j++)
            #pragma unroll
            for (int k = 0; k < 4; k++) acc[i][j][k] = 0.f;

    load_regs(0);
    for (int c = 0; c < NCH; c++) {
        store_smem();
        __syncthreads();
        if (c + 1 < NCH) load_regs(c + 1);

        #pragma unroll
        for (int ks = 0; ks < 4; ks++) {
            const uint32_t ko = ks * 32;
            uint32_t a[2][4], b[2][4];
            #pragma unroll
            for (int mf = 0; mf < 2; mf++)
                ldsm4(a[mf], sbase + saOff + mf * (16 * ROWA) + ko);
            #pragma unroll
            for (int g = 0; g < 2; g++)
                ldsm4t(b[g], sbase + sbOff + ks * (16 * ROWBT) + g * 32);
            #pragma unroll
            for (int mf = 0; mf < 2; mf++)
                #pragma unroll
                for (int nf = 0; nf < 4; nf++) {
                    uint32_t bf[2] = { b[nf >> 1][nf & 1], b[nf >> 1][2 + (nf & 1)] };
                    mma16816(acc[mf][nf], a[mf], bf);
                }
        }
        __syncthreads();
    }

    __half* dst = g_kwPartH[blockIdx.z];
    #pragma unroll
    for (int mf = 0; mf < 2; mf++) {
        const int r0 = m0 + warpM * 32 + mf * 16 + (lane >> 2);
        #pragma unroll
        for (int nf = 0; nf < 4; nf++) {
            const int cb = n0 + warpN * 32 + nf * 8 + (lane & 3) * 2;
            *(uint32_t*)&dst[(size_t)r0 * TT + cb] =
                pack2h(acc[mf][nf][0], acc[mf][nf][1]);
            *(uint32_t*)&dst[(size_t)(r0 + 8) * TT + cb] =
                pack2h(acc[mf][nf][2], acc[mf][nf][3]);
        }
    }
}

// kw rows: sum PROJ_Z fp16 partials + bias, L2-normalize, write fp16
__global__ __launch_bounds__(128)
void kw_norm_pack(const float* __restrict__ bias)
{
    const int w    = (blockIdx.x * blockDim.x + threadIdx.x) >> 5;
    const int lane = threadIdx.x & 31;
    if (w >= BN) return;
    const float4* b4 = (const float4*)bias;
    float4 v[4];
    float ss = 0.f;
    #pragma unroll
    for (int q = 0; q < 4; q++) {
        const int i = lane + 32 * q;
        float4 s = b4[i];
        #pragma unroll
        for (int z = 0; z < PROJ_Z; z++) {
            const uint2 pk = ((const uint2*)(g_kwPartH[z] + (size_t)w * TT))[i];
            const float2 f0 = __half22float2(*reinterpret_cast<const __half2*>(&pk.x));
            const float2 f1 = __half22float2(*reinterpret_cast<const __half2*>(&pk.y));
            s.x += f0.x; s.y += f0.y; s.z += f1.x; s.w += f1.y;
        }
        v[q] = s;
        ss += s.x * s.x + s.y * s.y + s.z * s.z + s.w * s.w;
    }
    #pragma unroll
    for (int o = 16; o > 0; o >>= 1) ss += __shfl_xor_sync(0xffffffffu, ss, o);
    const float inv = 1.f / fmaxf(sqrtf(ss), 1e-8f);
    #pragma unroll
    for (int q = 0; q < 4; q++) {
        const int e0 = (lane + 32 * q) * 4;
        const uint2 pk = make_uint2(pack2h(v[q].x * inv, v[q].y * inv),
                                    pack2h(v[q].z * inv, v[q].w * inv));
        *(uint2*)&g_kwH[(size_t)w * TT + e0] = pk;
    }
}

// emb prep: one warp per vocab row; normalized fp16 (embH) + row norm (g_norm)
__global__ __launch_bounds__(512)
void emb_prep(const float* __restrict__ emb)
{
    const int w    = (blockIdx.x * blockDim.x + threadIdx.x) >> 5;
    const int lane = threadIdx.x & 31;
    if (w >= VV) return;
    const float4* row = (const float4*)(emb + (size_t)w * TT);
    float4 v[4];
    float ss = 0.f;
    #pragma unroll
    for (int q = 0; q < 4; q++) {
        v[q] = row[lane + 32 * q];
        ss += v[q].x * v[q].x + v[q].y * v[q].y + v[q].z * v[q].z + v[q].w * v[q].w;
    }
    #pragma unroll
    for (int o = 16; o > 0; o >>= 1) ss += __shfl_xor_sync(0xffffffffu, ss, o);
    const float nrm = sqrtf(ss);
    const float inv = 1.f / fmaxf(nrm, 1e-8f);
    if (lane == 0) g_norm[w] = nrm;
    #pragma unroll
    for (int q = 0; q < 4; q++) {
        const int e0 = (lane + 32 * q) * 4;
        const uint2 pk = make_uint2(pack2h(v[q].x * inv, v[q].y * inv),
                                    pack2h(v[q].z * inv, v[q].w * inv));
        *(uint2*)&g_embH[(size_t)w * TT + e0] = pk;
    }
}

// =============================================================================
extern "C" void kernel_launch(void* const* d_in, const int* in_sizes, int n_in,
                              void* d_out, int out_size)
{
    const float* audio = (const float*)d_in[0];
    const float* W     = (const float*)d_in[1];
    const float* bias  = (const float*)d_in[2];
    const float* emb   = (const float*)d_in[3];
    float* out = (float*)d_out;

    static cudaStream_t s2 = nullptr, s3 = nullptr;
    static cudaEvent_t evFork = nullptr, evJoin = nullptr, evZero = nullptr;
    if (!s2) {
        cudaStreamCreateWithFlags(&s2, cudaStreamNonBlocking);
        cudaStreamCreateWithFlags(&s3, cudaStreamNonBlocking);
        cudaEventCreateWithFlags(&evFork, cudaEventDisableTiming);
        cudaEventCreateWithFlags(&evJoin, cudaEventDisableTiming);
        cudaEventCreateWithFlags(&evZero, cudaEventDisableTiming);
        cudaFuncSetAttribute(gemm1, cudaFuncAttributeMaxDynamicSharedMemorySize, SMEMSZ);
        cudaFuncSetAttribute(gemm2, cudaFuncAttributeMaxDynamicSharedMemorySize, SMEMSZ);
        cudaFuncSetAttribute(proj_gemm, cudaFuncAttributeMaxDynamicSharedMemorySize, SMEMSZ);
    }

    float* rowsum;
    cudaGetSymbolAddress((void**)&rowsum, g_rowsum);

    // ---- fork ----
    cudaEventRecord(evFork, 0);
    cudaStreamWaitEvent(s2, evFork, 0);
    cudaStreamWaitEvent(s3, evFork, 0);

    // side stream s2: emb prep (longest independent chain)
    emb_prep<<<VV / 16, 512, 0, s2>>>(emb);
    cudaEventRecord(evJoin, s2);

    // side stream s3: memsets needed by the GEMMs
    cudaMemsetAsync(rowsum, 0, BN * sizeof(float), s3);
    cudaMemsetAsync(out,    0, (size_t)out_size * sizeof(float), s3);
    cudaEventRecord(evZero, s3);

    // main chain: proj (direct fp32 read, fp16 partials) -> kw_norm
    proj_gemm<<<dim3(TT / 128, BN / 128, PROJ_Z), 512, SMEMSZ>>>(audio, W);
    kw_norm_pack<<<BN / 4, 128>>>(bias);

    // ---- join, then the two floor-bound GEMMs ----
    cudaStreamWaitEvent(0, evJoin, 0);
    cudaStreamWaitEvent(0, evZero, 0);
    // GEMM1: non-persistent (measured fastest), x = m-tiles, y = n-tiles
    gemm1<<<dim3(BN / 128, VV / 128), 512, SMEMSZ>>>(0);
    // GEMM2: x = n-tiles (4), y = m-tiles (8), z = split-K (9)
    gemm2<<<dim3(TT / 128, BN / 128, 9), 512, SMEMSZ>>>(out);
}

// round 16
// speedup vs baseline: 1.5679x; 1.5679x over previous
#include <cuda_runtime.h>
#include <cuda_fp16.h>
#include <cstdint>
#include <cstddef>

#define BN 1024
#define DD 768
#define TT 512
#define VV 49408

#define PROJ_Z 4

// ------------------------- static device workspace --------------------------
__device__ float g_rowsum[BN];             // softmax denominators (scaled)
__device__ float g_norm[VV];               // ||emb_v|| (fp32)
__device__ __half g_kwPartH[PROJ_Z][BN * TT];      // proj split-K partials (fp16)
__device__ __half g_kwH[BN * TT];                  // normalized kw, fp16
__device__ __half g_embH[(size_t)VV * TT];         // NORMALIZED emb [v][t], fp16
__device__ __half g_probs[(size_t)BN * VV];        // scaled probs * ||emb_v||, fp16

// ------------------------------ helpers -------------------------------------
__device__ __forceinline__ uint32_t smem_u32(const void* p) {
    uint32_t a;
    asm("{ .reg .u64 t; cvta.to.shared.u64 t, %1; cvt.u32.u64 %0, t; }"
        : "=r"(a) : "l"(p));
    return a;
}
__device__ __forceinline__ void cp16(uint32_t s, const void* g) {
    asm volatile("cp.async.cg.shared.global [%0], [%1], 16;" :: "r"(s), "l"(g));
}
__device__ __forceinline__ void ldsm4(uint32_t* r, uint32_t addr) {
    asm volatile("ldmatrix.sync.aligned.m8n8.x4.shared.b16 {%0,%1,%2,%3}, [%4];"
        : "=r"(r[0]), "=r"(r[1]), "=r"(r[2]), "=r"(r[3]) : "r"(addr));
}
__device__ __forceinline__ void ldsm4t(uint32_t* r, uint32_t addr) {
    asm volatile("ldmatrix.sync.aligned.m8n8.x4.trans.shared.b16 {%0,%1,%2,%3}, [%4];"
        : "=r"(r[0]), "=r"(r[1]), "=r"(r[2]), "=r"(r[3]) : "r"(addr));
}
__device__ __forceinline__ void mma16816(float* c, const uint32_t* a, const uint32_t* b) {
    asm volatile("mma.sync.aligned.m16n8k16.row.col.f32.f16.f16.f32 "
        "{%0,%1,%2,%3}, {%4,%5,%6,%7}, {%8,%9}, {%0,%1,%2,%3};"
        : "+f"(c[0]), "+f"(c[1]), "+f"(c[2]), "+f"(c[3])
        : "r"(a[0]), "r"(a[1]), "r"(a[2]), "r"(a[3]), "r"(b[0]), "r"(b[1]));
}
__device__ __forceinline__ uint32_t pack2h(float a, float b) {
    const __half2 h = __floats2half2_rn(a, b);
    return *reinterpret_cast<const uint32_t*>(&h);
}
__device__ __forceinline__ uint4 cvt8(const float4 f0, const float4 f1) {
    return make_uint4(pack2h(f0.x, f0.y), pack2h(f0.z, f0.w),
                      pack2h(f1.x, f1.y), pack2h(f1.z, f1.w));
}

#define ROWA   144
#define ROWBT  272
#define PLANE  18432
#define STAGE  (2 * PLANE)            // 36864
#define NSTAGE 2
#define SMEMSZ (NSTAGE * STAGE + 512) // 74240 -> 2 CTAs/SM

#define PSCALE 16384.f

// =============================================================================
// GEMM1 (non-persistent): logits + exp epilogue.
// Grid (BN/128, VV/128), 512 thr, warp 32x32, FULLY-UNROLLED 8-chunk K loop.
// =============================================================================
__global__ __launch_bounds__(512, 2) void gemm1(int dummy)
{
    extern __shared__ char smem[];
    const uint32_t sbase = smem_u32(smem);
    const int tid = threadIdx.x;
    const int lane = tid & 31, wid = tid >> 5;
    const int warpM = wid & 3, warpN = wid >> 2;
    const int m0 = blockIdx.x * 128, n0 = blockIdx.y * 128;

    float* sNorm = (float*)(smem + NSTAGE * STAGE);
    if (tid < 128) sNorm[tid] = g_norm[n0 + tid];

    const uint32_t ch   = tid & 7;
    const uint32_t rowA = tid >> 3;
    uint32_t aOff = (uint32_t)(m0 + rowA) * TT + ch * 8;
    uint32_t bOff = (uint32_t)(n0 + rowA) * TT + ch * 8;
    const uint32_t aSo = rowA * ROWA + ch * 16;

    auto issue = [&](uint32_t st) {
        #pragma unroll
        for (int p = 0; p < 2; p++) {
            cp16(st + aSo + p * (64 * ROWA), g_kwH  + aOff + p * (64 * TT));
            cp16(st + PLANE + aSo + p * (64 * ROWA), g_embH + bOff + p * (64 * TT));
        }
        aOff += 64;
        bOff += 64;
    };

    const uint32_t saOff = (uint32_t)(warpM * 32 + (lane & 15)) * ROWA + ((lane >> 4) << 4);
    const uint32_t sbOff = PLANE + (uint32_t)(warpN * 32 + (lane & 15)) * ROWA
                         + ((lane >> 4) << 4);

    float acc[2][4][4];
    #pragma unroll
    for (int i = 0; i < 2; i++)
        #pragma unroll
        for (int j = 0; j < 4; j++)
            #pragma unroll
            for (int k = 0; k < 4; k++) acc[i][j][k] = 0.f;

    issue(sbase);
    asm volatile("cp.async.commit_group;" ::: "memory");
    issue(sbase + STAGE);
    asm volatile("cp.async.commit_group;" ::: "memory");

    #pragma unroll
    for (int c = 0; c < TT / 64; c++) {
        asm volatile("cp.async.wait_group 1;" ::: "memory");
        __syncthreads();
        const uint32_t st = sbase + (uint32_t)(c & 1) * STAGE;

        #pragma unroll
        for (int ks = 0; ks < 4; ks++) {
            const uint32_t ko = ks * 32;
            uint32_t a[2][4], b[2][4];
            #pragma unroll
            for (int mf = 0; mf < 2; mf++)
                ldsm4(a[mf], st + saOff + mf * (16 * ROWA) + ko);
            #pragma unroll
            for (int g = 0; g < 2; g++)
                ldsm4(b[g], st + sbOff + g * (16 * ROWA) + ko);
            #pragma unroll
            for (int mf = 0; mf < 2; mf++)
                #pragma unroll
                for (int nf = 0; nf < 4; nf++) {
                    uint32_t bf[2] = { b[nf >> 1][nf & 1], b[nf >> 1][2 + (nf & 1)] };
                    mma16816(acc[mf][nf], a[mf], bf);
                }
        }
        __syncthreads();
        if (c + 2 < TT / 64) issue(st);
        asm volatile("cp.async.commit_group;" ::: "memory");
    }

    #pragma unroll
    for (int mf = 0; mf < 2; mf++) {
        const int r0 = m0 + warpM * 32 + mf * 16 + (lane >> 2);
        float rs0 = 0.f, rs1 = 0.f;
        #pragma unroll
        for (int nf = 0; nf < 4; nf++) {
            const int cl = warpN * 32 + nf * 8 + (lane & 3) * 2;
            const int cb = n0 + cl;
            const float e0 = __expf(acc[mf][nf][0] * 10.f - 10.f) * PSCALE;
            const float e1 = __expf(acc[mf][nf][1] * 10.f - 10.f) * PSCALE;
            const float e2 = __expf(acc[mf][nf][2] * 10.f - 10.f) * PSCALE;
            const float e3 = __expf(acc[mf][nf][3] * 10.f - 10.f) * PSCALE;
            rs0 += e0 + e1;  rs1 += e2 + e3;
            const float w0 = sNorm[cl], w1 = sNorm[cl + 1];
            *(uint32_t*)&g_probs[(size_t)r0 * VV + cb] = pack2h(e0 * w0, e1 * w1);
            *(uint32_t*)&g_probs[(size_t)(r0 + 8) * VV + cb] = pack2h(e2 * w0, e3 * w1);
        }
        rs0 += __shfl_xor_sync(0xffffffffu, rs0, 1);
        rs0 += __shfl_xor_sync(0xffffffffu, rs0, 2);
        rs1 += __shfl_xor_sync(0xffffffffu, rs1, 1);
        rs1 += __shfl_xor_sync(0xffffffffu, rs1, 2);
        if ((lane & 3) == 0) {
            atomicAdd(&g_rowsum[r0],     rs0);
            atomicAdd(&g_rowsum[r0 + 8], rs1);
        }
    }
}

// =============================================================================
// GEMM2: VQ split-K (A=probs, B=embH trans) -> (1/rowsum)*atomicAdd out
// =============================================================================
__global__ __launch_bounds__(512, 2) void gemm2(float* __restrict__ outf)
{
    constexpr int NCHT = VV / 64;
    extern __shared__ char smem[];
    const uint32_t sbase = smem_u32(smem);
    const int tid = threadIdx.x;
    const int lane = tid & 31, wid = tid >> 5;
    const int warpM = wid & 3, warpN = wid >> 2;

    const int n0 = blockIdx.x * 128, m0 = blockIdx.y * 128;
    const int c0 = (int)(((long)NCHT * blockIdx.z) / gridDim.z);
    const int c1 = (int)(((long)NCHT * (blockIdx.z + 1)) / gridDim.z);
    const int nch = c1 - c0;

    const uint32_t ch   = tid & 7;
    const uint32_t rowA = tid >> 3;
    uint32_t aOff = (uint32_t)(m0 + rowA) * VV + (uint32_t)c0 * 64 + ch * 8;
    const uint32_t aSo = rowA * ROWA + ch * 16;
    const uint32_t rb = tid >> 4, cb2 = tid & 15;
    uint32_t bOff = ((uint32_t)c0 * 64 + rb) * TT + (uint32_t)n0 + cb2 * 8;
    const uint32_t bSo = rb * ROWBT + cb2 * 16;

    auto issue = [&](uint32_t st) {
        #pragma unroll
        for (int p = 0; p < 2; p++) {
            cp16(st + aSo + p * (64 * ROWA), g_probs + aOff + p * (64 * VV));
            cp16(st + PLANE + bSo + p * (32 * ROWBT), g_embH + bOff + p * (32 * TT));
        }
        aOff += 64;
        bOff += 64 * TT;
    };

    const uint32_t saOff = (uint32_t)(warpM * 32 + (lane & 15)) * ROWA + ((lane >> 4) << 4);
    const uint32_t sbOff = PLANE + (uint32_t)((lane & 7) + ((lane >> 4) << 3)) * ROWBT
                         + (uint32_t)(warpN * 32 + ((lane >> 3) & 1) * 8) * 2;

    float acc[2][4][4];
    #pragma unroll
    for (int i = 0; i < 2; i++)
        #pragma unroll
        for (int j = 0; j < 4; j++)
            #pragma unroll
            for (int k = 0; k < 4; k++) acc[i][j][k] = 0.f;

    issue(sbase);
    asm volatile("cp.async.commit_group;" ::: "memory");
    issue(sbase + STAGE);
    asm volatile("cp.async.commit_group;" ::: "memory");

    for (int c = 0; c < nch; c++) {
        asm volatile("cp.async.wait_group 1;" ::: "memory");
        __syncthreads();
        const uint32_t st = sbase + (uint32_t)(c & 1) * STAGE;

        #pragma unroll
        for (int ks = 0; ks < 4; ks++) {
            const uint32_t ko = ks * 32;
            uint32_t a[2][4], b[2][4];
            #pragma unroll
            for (int mf = 0; mf < 2; mf++)
                ldsm4(a[mf], st + saOff + mf * (16 * ROWA) + ko);
            #pragma unroll
            for (int g = 0; g < 2; g++)
                ldsm4t(b[g], st + sbOff + ks * (16 * ROWBT) + g * 32);
            #pragma unroll
            for (int mf = 0; mf < 2; mf++)
                #pragma unroll
                for (int nf = 0; nf < 4; nf++) {
                    uint32_t bf[2] = { b[nf >> 1][nf & 1], b[nf >> 1][2 + (nf & 1)] };
                    mma16816(acc[mf][nf], a[mf], bf);
                }
        }
        __syncthreads();
        if (c + 2 < nch) issue(st);
        asm volatile("cp.async.commit_group;" ::: "memory");
    }

    #pragma unroll
    for (int mf = 0; mf < 2; mf++) {
        const int r0 = m0 + warpM * 32 + mf * 16 + (lane >> 2);
        const float s0 = 1.f / g_rowsum[r0];
        const float s1 = 1.f / g_rowsum[r0 + 8];
        #pragma unroll
        for (int nf = 0; nf < 4; nf++) {
            const int cb = n0 + warpN * 32 + nf * 8 + (lane & 3) * 2;
            atomicAdd(&outf[(size_t)r0 * TT + cb],           acc[mf][nf][0] * s0);
            atomicAdd(&outf[(size_t)r0 * TT + cb + 1],       acc[mf][nf][1] * s0);
            atomicAdd(&outf[(size_t)(r0 + 8) * TT + cb],     acc[mf][nf][2] * s1);
            atomicAdd(&outf[(size_t)(r0 + 8) * TT + cb + 1], acc[mf][nf][3] * s1);
        }
    }
}

// =============================================================================
// Projection on tensor path, on-the-fly fp32->fp16 conversion, fp16 partials.
// =============================================================================
__global__ __launch_bounds__(512, 1)
void proj_gemm(const float* __restrict__ audio, const float* __restrict__ W)
{
    constexpr int NCH = (DD / 64) / PROJ_Z;   // 3
    extern __shared__ char smem[];
    const uint32_t sbase = smem_u32(smem);
    const int tid = threadIdx.x;
    const int lane = tid & 31, wid = tid >> 5;
    const int warpM = wid & 3, warpN = wid >> 2;

    const int n0 = blockIdx.x * 128, m0 = blockIdx.y * 128;
    const int c0 = blockIdx.z * NCH;

    const uint32_t ch   = tid & 7;
    const uint32_t rowA = tid >> 3;
    const uint32_t aSo = rowA * ROWA + ch * 16;
    const uint32_t rb = tid >> 4, cb2 = tid & 15;
    const uint32_t bSo = rb * ROWBT + cb2 * 16;

    float4 ra[2][2], rbv[2][2];
    auto load_regs = [&](int c) {
        #pragma unroll
        for (int p = 0; p < 2; p++) {
            const float* pa = audio + (size_t)(m0 + rowA + p * 64) * DD
                            + (c0 + c) * 64 + ch * 8;
            ra[p][0] = ((const float4*)pa)[0];
            ra[p][1] = ((const float4*)pa)[1];
            const float* pb = W + (size_t)((c0 + c) * 64 + rb + p * 32) * TT
                            + n0 + cb2 * 8;
            rbv[p][0] = ((const float4*)pb)[0];
            rbv[p][1] = ((const float4*)pb)[1];
        }
    };
    auto store_smem = [&]() {
        #pragma unroll
        for (int p = 0; p < 2; p++) {
            *(uint4*)(smem + aSo + p * (64 * ROWA)) = cvt8(ra[p][0], ra[p][1]);
            *(uint4*)(smem + PLANE + bSo + p * (32 * ROWBT)) = cvt8(rbv[p][0], rbv[p][1]);
        }
    };

    const uint32_t saOff = (uint32_t)(warpM * 32 + (lane & 15)) * ROWA + ((lane >> 4) << 4);
    const uint32_t sbOff = PLANE + (uint32_t)((lane & 7) + ((lane >> 4) << 3)) * ROWBT
                         + (uint32_t)(warpN * 32 + ((lane >> 3) & 1) * 8) * 2;

    float acc[2][4][4];
    #pragma unroll
    for (int i = 0; i < 2; i++)
        #pragma unroll
        for (int j = 0; j < 4; j++)
            #pragma unroll
            for (int k = 0; k < 4; k++) acc[i][j][k] = 0.f;

    load_regs(0);
    for (int c = 0; c < NCH; c++) {
        store_smem();
        __syncthreads();
        if (c + 1 < NCH) load_regs(c + 1);

        #pragma unroll
        for (int ks = 0; ks < 4; ks++) {
            const uint32_t ko = ks * 32;
            uint32_t a[2][4], b[2][4];
            #pragma unroll
            for (int mf = 0; mf < 2; mf++)
                ldsm4(a[mf], sbase + saOff + mf * (16 * ROWA) + ko);
            #pragma unroll
            for (int g = 0; g < 2; g++)
                ldsm4t(b[g], sbase + sbOff + ks * (16 * ROWBT) + g * 32);
            #pragma unroll
            for (int mf = 0; mf < 2; mf++)
                #pragma unroll
                for (int nf = 0; nf < 4; nf++) {
                    uint32_t bf[2] = { b[nf >> 1][nf & 1], b[nf >> 1][2 + (nf & 1)] };
                    mma16816(acc[mf][nf], a[mf], bf);
                }
        }
        __syncthreads();
    }

    __half* dst = g_kwPartH[blockIdx.z];
    #pragma unroll
    for (int mf = 0; mf < 2; mf++) {
        const int r0 = m0 + warpM * 32 + mf * 16 + (lane >> 2);
        #pragma unroll
        for (int nf = 0; nf < 4; nf++) {
            const int cb = n0 + warpN * 32 + nf * 8 + (lane & 3) * 2;
            *(uint32_t*)&dst[(size_t)r0 * TT + cb] =
                pack2h(acc[mf][nf][0], acc[mf][nf][1]);
            *(uint32_t*)&dst[(size_t)(r0 + 8) * TT + cb] =
                pack2h(acc[mf][nf][2], acc[mf][nf][3]);
        }
    }
}

// kw rows: sum PROJ_Z fp16 partials + bias, L2-normalize, write fp16
__global__ __launch_bounds__(128)
void kw_norm_pack(const float* __restrict__ bias)
{
    const int w    = (blockIdx.x * blockDim.x + threadIdx.x) >> 5;
    const int lane = threadIdx.x & 31;
    if (w >= BN) return;
    const float4* b4 = (const float4*)bias;
    float4 v[4];
    float ss = 0.f;
    #pragma unroll
    for (int q = 0; q < 4; q++) {
        const int i = lane + 32 * q;
        float4 s = b4[i];
        #pragma unroll
        for (int z = 0; z < PROJ_Z; z++) {
            const uint2 pk = ((const uint2*)(g_kwPartH[z] + (size_t)w * TT))[i];
            const float2 f0 = __half22float2(*reinterpret_cast<const __half2*>(&pk.x));
            const float2 f1 = __half22float2(*reinterpret_cast<const __half2*>(&pk.y));
            s.x += f0.x; s.y += f0.y; s.z += f1.x; s.w += f1.y;
        }
        v[q] = s;
        ss += s.x * s.x + s.y * s.y + s.z * s.z + s.w * s.w;
    }
    #pragma unroll
    for (int o = 16; o > 0; o >>= 1) ss += __shfl_xor_sync(0xffffffffu, ss, o);
    const float inv = 1.f / fmaxf(sqrtf(ss), 1e-8f);
    #pragma unroll
    for (int q = 0; q < 4; q++) {
        const int e0 = (lane + 32 * q) * 4;
        const uint2 pk = make_uint2(pack2h(v[q].x * inv, v[q].y * inv),
                                    pack2h(v[q].z * inv, v[q].w * inv));
        *(uint2*)&g_kwH[(size_t)w * TT + e0] = pk;
    }
}

// emb prep: one warp per vocab row; normalized fp16 (embH) + row norm (g_norm)
__global__ __launch_bounds__(512)
void emb_prep(const float* __restrict__ emb)
{
    const int w    = (blockIdx.x * blockDim.x + threadIdx.x) >> 5;
    const int lane = threadIdx.x & 31;
    if (w >= VV) return;
    const float4* row = (const float4*)(emb + (size_t)w * TT);
    float4 v[4];
    float ss = 0.f;
    #pragma unroll
    for (int q = 0; q < 4; q++) {
        v[q] = row[lane + 32 * q];
        ss += v[q].x * v[q].x + v[q].y * v[q].y + v[q].z * v[q].z + v[q].w * v[q].w;
    }
    #pragma unroll
    for (int o = 16; o > 0; o >>= 1) ss += __shfl_xor_sync(0xffffffffu, ss, o);
    const float nrm = sqrtf(ss);
    const float inv = 1.f / fmaxf(nrm, 1e-8f);
    if (lane == 0) g_norm[w] = nrm;
    #pragma unroll
    for (int q = 0; q < 4; q++) {
        const int e0 = (lane + 32 * q) * 4;
        const uint2 pk = make_uint2(pack2h(v[q].x * inv, v[q].y * inv),
                                    pack2h(v[q].z * inv, v[q].w * inv));
        *(uint2*)&g_embH[(size_t)w * TT + e0] = pk;
    }
}

// =============================================================================
extern "C" void kernel_launch(void* const* d_in, const int* in_sizes, int n_in,
                              void* d_out, int out_size)
{
    const float* audio = (const float*)d_in[0];
    const float* W     = (const float*)d_in[1];
    const float* bias  = (const float*)d_in[2];
    const float* emb   = (const float*)d_in[3];
    float* out = (float*)d_out;

    static cudaStream_t s2 = nullptr, s3 = nullptr;
    static cudaEvent_t evFork = nullptr, evJoin = nullptr, evZero = nullptr;
    if (!s2) {
        cudaStreamCreateWithFlags(&s2, cudaStreamNonBlocking);
        cudaStreamCreateWithFlags(&s3, cudaStreamNonBlocking);
        cudaEventCreateWithFlags(&evFork, cudaEventDisableTiming);
        cudaEventCreateWithFlags(&evJoin, cudaEventDisableTiming);
        cudaEventCreateWithFlags(&evZero, cudaEventDisableTiming);
        cudaFuncSetAttribute(gemm1, cudaFuncAttributeMaxDynamicSharedMemorySize, SMEMSZ);
        cudaFuncSetAttribute(gemm2, cudaFuncAttributeMaxDynamicSharedMemorySize, SMEMSZ);
        cudaFuncSetAttribute(proj_gemm, cudaFuncAttributeMaxDynamicSharedMemorySize, SMEMSZ);
    }

    float* rowsum;
    cudaGetSymbolAddress((void**)&rowsum, g_rowsum);

    // ---- fork ----
    cudaEventRecord(evFork, 0);
    cudaStreamWaitEvent(s2, evFork, 0);
    cudaStreamWaitEvent(s3, evFork, 0);

    // side stream s2: emb prep (longest independent chain)
    emb_prep<<<VV / 16, 512, 0, s2>>>(emb);
    cudaEventRecord(evJoin, s2);

    // side stream s3: memsets needed by the GEMMs
    cudaMemsetAsync(rowsum, 0, BN * sizeof(float), s3);
    cudaMemsetAsync(out,    0, (size_t)out_size * sizeof(float), s3);
    cudaEventRecord(evZero, s3);

    // main chain: proj (direct fp32 read, fp16 partials) -> kw_norm
    proj_gemm<<<dim3(TT / 128, BN / 128, PROJ_Z), 512, SMEMSZ>>>(audio, W);
    kw_norm_pack<<<BN / 4, 128>>>(bias);

    // ---- join, then the two floor-bound GEMMs ----
    cudaStreamWaitEvent(0, evJoin, 0);
    cudaStreamWaitEvent(0, evZero, 0);
    // GEMM1: non-persistent, fully unrolled mainloop
    gemm1<<<dim3(BN / 128, VV / 128), 512, SMEMSZ>>>(0);
    // GEMM2: x = n-tiles (4), y = m-tiles (8), z = split-K (9)
    gemm2<<<dim3(TT / 128, BN / 128, 9), 512, SMEMSZ>>>(out);
}